// round 5
// baseline (speedup 1.0000x reference)
#include <cuda_runtime.h>
#include <cuda_bf16.h>
#include <math.h>
#include <stdint.h>

// ---------------------------------------------------------------------------
// Problem constants
// ---------------------------------------------------------------------------
#define MAX_N  50048
#define MAX_E  800000
#define MAX_NI 2048

// ---------------------------------------------------------------------------
// Static device scratch
// ---------------------------------------------------------------------------
__device__ float g_xa  [MAX_N * 256];
__device__ float g_xp  [MAX_N * 256];
__device__ float g_qa  [MAX_N * 256];
__device__ float g_kv  [MAX_N * 512];   // per node: [ke_h0|ke_h1|ve_h0|ve_h1]
__device__ float g_agg [MAX_N * 256];   // gelu(attention out)
__device__ float g_za  [MAX_N * 256];
__device__ float g_zin [MAX_NI * 256];
__device__ float g_wft [512 * 256];     // fused k/v weights, TRANSPOSED [out][in]
__device__ float g_bf  [512];
__device__ float g_wina_t[256 * 128];
__device__ float g_winp_t[256 * 128];
__device__ float g_wq_t  [256 * 256];
__device__ float g_wout_t[256 * 256];
__device__ int   g_deg [MAX_N + 1];
__device__ int   g_off [MAX_N + 1];
__device__ int   g_cur [MAX_N];
__device__ int   g_csr [MAX_E];

// ===========================================================================
// Split-bf16 tensor-core NT GEMM:  C[M,N] = act( A[M,K] * B[N,K]^T + bias )
// smem rows hold [hi(16) | lo(16)] bf16 per 16-k chunk, stride 40 (ldmatrix
// conflict-free). Fragments via ldmatrix.x4. Per k16: Ah*Bh + Ah*Bl + Al*Bh.
// Block 128x128, 8 warps (4m x 2n), warp tile 32x64.
// act: 0 none, 1 relu, 2 sigmoid, 3 gated residual ga*v+(1-ga)*aux
// ===========================================================================
#define SMSTR 40   // bf16 stride per row (16 hi + 16 lo + 8 pad)

__device__ __forceinline__ uint32_t smem_u32(const void* p) {
    uint32_t a;
    asm("{ .reg .u64 t; cvta.to.shared.u64 t, %1; cvt.u32.u64 %0, t; }"
        : "=r"(a) : "l"(p));
    return a;
}

#define LDSM4(r0, r1, r2, r3, addr) \
    asm volatile("ldmatrix.sync.aligned.m8n8.x4.shared.b16 {%0,%1,%2,%3}, [%4];" \
                 : "=r"(r0), "=r"(r1), "=r"(r2), "=r"(r3) : "r"(addr))

#define MMA16816(acc, a0, a1, a2, a3, b0, b1) \
    asm volatile("mma.sync.aligned.m16n8k16.row.col.f32.bf16.bf16.f32 " \
                 "{%0,%1,%2,%3}, {%4,%5,%6,%7}, {%8,%9}, {%0,%1,%2,%3};\n" \
                 : "+f"((acc)[0]), "+f"((acc)[1]), "+f"((acc)[2]), "+f"((acc)[3]) \
                 : "r"(a0), "r"(a1), "r"(a2), "r"(a3), "r"(b0), "r"(b1))

__global__ void __launch_bounds__(256, 2)
mm_nt(int M, int N, int K,
      const float* __restrict__ A, int lda,
      const float* __restrict__ B, int ldb,
      float* __restrict__ C, int ldc,
      const float* __restrict__ bias, int act,
      const float* __restrict__ aux, const float* __restrict__ skipp)
{
    __shared__ __align__(16) __nv_bfloat16 As[128 * SMSTR];
    __shared__ __align__(16) __nv_bfloat16 Bs[128 * SMSTR];

    const int m0 = blockIdx.y * 128;
    const int n0 = blockIdx.x * 128;
    const int tid  = threadIdx.x;
    const int warp = tid >> 5, lane = tid & 31;
    const int g  = lane >> 2, tg = lane & 3;
    const int wm = warp >> 1, wn = warp & 1;        // 4m x 2n warps
    const int l15 = lane & 15, l16 = lane >> 4;

    const uint32_t asb = smem_u32(As), bsb = smem_u32(Bs);

    float acc[2][8][4];
#pragma unroll
    for (int i = 0; i < 2; i++)
#pragma unroll
        for (int j = 0; j < 8; j++)
#pragma unroll
            for (int e = 0; e < 4; e++) acc[i][j][e] = 0.f;

    // staging map: each thread = one row-half (8 k) of A and of B
    const int srow = tid >> 1, shalf = tid & 1;
    const float4 z4 = make_float4(0.f, 0.f, 0.f, 0.f);
    float4 ra[2], rb[2];

    const int KT = K >> 4;
    const int mrows = (M - m0 > 128) ? 128 : (M - m0);
    const int nrows = (N - n0 > 128) ? 128 : (N - n0);
    const bool aok = srow < mrows, bok = srow < nrows;
    const float* ap = A + (size_t)(m0 + srow) * lda + shalf * 8;
    const float* bp = B + (size_t)(n0 + srow) * ldb + shalf * 8;

    // prefetch tile 0
    ra[0] = aok ? *(const float4*)(ap + 0) : z4;
    ra[1] = aok ? *(const float4*)(ap + 4) : z4;
    rb[0] = bok ? *(const float4*)(bp + 0) : z4;
    rb[1] = bok ? *(const float4*)(bp + 4) : z4;

    for (int kt = 0; kt < KT; kt++) {
        // ---- convert + store (hi at col k, lo at col 16+k) ----
#pragma unroll
        for (int q = 0; q < 2; q++) {
            float va[4] = {ra[q].x, ra[q].y, ra[q].z, ra[q].w};
            float vb[4] = {rb[q].x, rb[q].y, rb[q].z, rb[q].w};
            uint64_t ah = 0, al = 0, bh = 0, bl = 0;
#pragma unroll
            for (int j = 0; j < 4; j++) {
                __nv_bfloat16 h = __float2bfloat16_rn(va[j]);
                __nv_bfloat16 l = __float2bfloat16_rn(va[j] - __bfloat162float(h));
                ah |= (uint64_t)__bfloat16_as_ushort(h) << (16 * j);
                al |= (uint64_t)__bfloat16_as_ushort(l) << (16 * j);
                h = __float2bfloat16_rn(vb[j]);
                l = __float2bfloat16_rn(vb[j] - __bfloat162float(h));
                bh |= (uint64_t)__bfloat16_as_ushort(h) << (16 * j);
                bl |= (uint64_t)__bfloat16_as_ushort(l) << (16 * j);
            }
            int kc = shalf * 8 + 4 * q;          // 0..15
            *(uint64_t*)&As[srow * SMSTR + kc]      = ah;
            *(uint64_t*)&As[srow * SMSTR + 16 + kc] = al;
            *(uint64_t*)&Bs[srow * SMSTR + kc]      = bh;
            *(uint64_t*)&Bs[srow * SMSTR + 16 + kc] = bl;
        }
        __syncthreads();

        // ---- prefetch next tile ----
        if (kt + 1 < KT) {
            const float* a2 = ap + (kt + 1) * 16;
            const float* b2 = bp + (kt + 1) * 16;
            ra[0] = aok ? *(const float4*)(a2 + 0) : z4;
            ra[1] = aok ? *(const float4*)(a2 + 4) : z4;
            rb[0] = bok ? *(const float4*)(b2 + 0) : z4;
            rb[1] = bok ? *(const float4*)(b2 + 4) : z4;
        }

        // ---- fragments via ldmatrix + 3-term compensated mma ----
        uint32_t ahf[2][4], alf[2][4];
#pragma unroll
        for (int mt = 0; mt < 2; mt++) {
            int row = wm * 32 + mt * 16 + l15;
            uint32_t ah_a = asb + row * (SMSTR * 2) + l16 * 16;
            uint32_t al_a = ah_a + 32;
            LDSM4(ahf[mt][0], ahf[mt][1], ahf[mt][2], ahf[mt][3], ah_a);
            LDSM4(alf[mt][0], alf[mt][1], alf[mt][2], alf[mt][3], al_a);
        }
#pragma unroll
        for (int np = 0; np < 4; np++) {
            uint32_t bhf[4], blf[4];
            int row = wn * 64 + np * 16 + l15;
            uint32_t bh_a = bsb + row * (SMSTR * 2) + l16 * 16;
            uint32_t bl_a = bh_a + 32;
            LDSM4(bhf[0], bhf[1], bhf[2], bhf[3], bh_a);
            LDSM4(blf[0], blf[1], blf[2], blf[3], bl_a);
#pragma unroll
            for (int mt = 0; mt < 2; mt++) {
#pragma unroll
                for (int j = 0; j < 2; j++) {
                    float* ac = acc[mt][np * 2 + j];
                    MMA16816(ac, ahf[mt][0], ahf[mt][1], ahf[mt][2], ahf[mt][3],
                             bhf[j], bhf[2 + j]);
                    MMA16816(ac, ahf[mt][0], ahf[mt][1], ahf[mt][2], ahf[mt][3],
                             blf[j], blf[2 + j]);
                    MMA16816(ac, alf[mt][0], alf[mt][1], alf[mt][2], alf[mt][3],
                             bhf[j], bhf[2 + j]);
                }
            }
        }
        __syncthreads();
    }

    // ---- epilogue ----
    float ga = 0.f;
    if (act == 3) ga = 1.f / (1.f + __expf(-skipp[0]));

#pragma unroll
    for (int mt = 0; mt < 2; mt++) {
#pragma unroll
        for (int nt = 0; nt < 8; nt++) {
            int r0 = m0 + wm * 32 + mt * 16 + g;
            int cc = n0 + wn * 64 + nt * 8 + 2 * tg;
            if (cc < N) {
                float b0 = bias ? bias[cc] : 0.f;
                float b1 = bias ? bias[cc + 1] : 0.f;
                float v0 = acc[mt][nt][0] + b0, v1 = acc[mt][nt][1] + b1;
                float v2 = acc[mt][nt][2] + b0, v3 = acc[mt][nt][3] + b1;
                if (act == 1) {
                    v0 = fmaxf(v0, 0.f); v1 = fmaxf(v1, 0.f);
                    v2 = fmaxf(v2, 0.f); v3 = fmaxf(v3, 0.f);
                } else if (act == 2) {
                    v0 = 1.f / (1.f + __expf(-v0)); v1 = 1.f / (1.f + __expf(-v1));
                    v2 = 1.f / (1.f + __expf(-v2)); v3 = 1.f / (1.f + __expf(-v3));
                } else if (act == 3) {
                    if (r0 < M) {
                        v0 = ga * v0 + (1.f - ga) * aux[(size_t)r0 * 256 + cc];
                        v1 = ga * v1 + (1.f - ga) * aux[(size_t)r0 * 256 + cc + 1];
                    }
                    if (r0 + 8 < M) {
                        v2 = ga * v2 + (1.f - ga) * aux[(size_t)(r0 + 8) * 256 + cc];
                        v3 = ga * v3 + (1.f - ga) * aux[(size_t)(r0 + 8) * 256 + cc + 1];
                    }
                }
                if (r0 < M)     { float2 p = {v0, v1}; *(float2*)&C[(size_t)r0 * ldc + cc] = p; }
                if (r0 + 8 < M) { float2 p = {v2, v3}; *(float2*)&C[(size_t)(r0 + 8) * ldc + cc] = p; }
            }
        }
    }
}

// ---------------------------------------------------------------------------
// Small weight transpose: out[n*K + k] = in[k*ldin + n]   (in is [K, N])
// ---------------------------------------------------------------------------
__global__ void tr_kernel(const float* __restrict__ in, int ldin,
                          float* __restrict__ out, int K, int N)
{
    __shared__ float t[32][33];
    int bx = blockIdx.x * 32, by = blockIdx.y * 32;
    int x = bx + threadIdx.x;
    for (int dy = 0; dy < 32; dy += 8) {
        int y = by + threadIdx.y + dy;
        if (x < N && y < K) t[threadIdx.y + dy][threadIdx.x] = in[(size_t)y * ldin + x];
    }
    __syncthreads();
    int x2 = by + threadIdx.x;
    for (int dy = 0; dy < 32; dy += 8) {
        int y2 = bx + threadIdx.y + dy;
        if (x2 < K && y2 < N) out[(size_t)y2 * K + x2] = t[threadIdx.x][threadIdx.y + dy];
    }
}

// ---------------------------------------------------------------------------
// Fused relation weights (transposed output):
// g_wft[c][r] = sum_d Wkqv_p[r][part + h*128 + d] * R[h][d][e]
// ---------------------------------------------------------------------------
__global__ void fuse_kernel(const float* __restrict__ Wkqv_p,
                            const float* __restrict__ Rk,
                            const float* __restrict__ Rv)
{
    int idx = blockIdx.x * 256 + threadIdx.x;     // 512*256
    int c = idx >> 8, r = idx & 255;
    int isv = c >> 8, h = (c >> 7) & 1, e = c & 127;
    const float* R = (isv ? Rv : Rk) + h * 16384;
    const float* w = Wkqv_p + (size_t)r * 768 + (isv ? 512 : 0) + h * 128;
    float s = 0.f;
#pragma unroll 8
    for (int d = 0; d < 128; d++) s += w[d] * R[d * 128 + e];
    g_wft[c * 256 + r] = s;
}

__global__ void bias_fuse_kernel(const float* __restrict__ bkqv,
                                 const float* __restrict__ Rk,
                                 const float* __restrict__ Rv)
{
    int h = blockIdx.x & 1, isv = blockIdx.x >> 1;
    const float* R = (isv ? Rv : Rk) + h * 16384;
    const float* b = bkqv + (isv ? 512 : 0) + h * 128;
    int e = threadIdx.x;
    float s = 0.f;
#pragma unroll 8
    for (int d = 0; d < 128; d++) s += b[d] * R[d * 128 + e];
    g_bf[isv * 256 + h * 128 + e] = s;
}

// ---------------------------------------------------------------------------
// CSR build
// ---------------------------------------------------------------------------
__global__ void zero_deg_kernel(int n)
{
    int i = blockIdx.x * blockDim.x + threadIdx.x;
    if (i <= n) g_deg[i] = 0;
}
__global__ void hist_kernel(const int* __restrict__ dst, int E)
{
    int e = blockIdx.x * blockDim.x + threadIdx.x;
    if (e < E) atomicAdd(&g_deg[dst[e]], 1);
}
__global__ void __launch_bounds__(1024) scan_kernel(int n)
{
    __shared__ int part[1024];
    int t = threadIdx.x;
    int chunk = (n + 1023) >> 10;
    int b = t * chunk, e = min(b + chunk, n);
    int s = 0;
    for (int i = b; i < e; i++) s += g_deg[i];
    part[t] = s;
    __syncthreads();
    for (int o = 1; o < 1024; o <<= 1) {
        int v = (t >= o) ? part[t - o] : 0;
        __syncthreads();
        part[t] += v;
        __syncthreads();
    }
    int run = (t == 0) ? 0 : part[t - 1];
    for (int i = b; i < e; i++) {
        g_off[i] = run; g_cur[i] = run; run += g_deg[i];
    }
    if (t == 0) g_off[n] = part[1023];
}
__global__ void scatter_kernel(const int* __restrict__ src,
                               const int* __restrict__ dst, int E)
{
    int e = blockIdx.x * blockDim.x + threadIdx.x;
    if (e < E) {
        int p = atomicAdd(&g_cur[dst[e]], 1);
        g_csr[p] = src[e];
    }
}

// ---------------------------------------------------------------------------
// Attention: warp per (dst, head), single-pass online softmax, gelu fused.
// ---------------------------------------------------------------------------
__global__ void attn_kernel(int Na, const float* __restrict__ p_rel)
{
    int gw = (blockIdx.x * 256 + threadIdx.x) >> 5;
    int lane = threadIdx.x & 31;
    if (gw >= Na * 2) return;
    int dst = gw >> 1, h = gw & 1;

    int beg = g_off[dst], end = g_off[dst + 1];
    float scale = p_rel[h] * 0.08838834764831845f;   // p / sqrt(128)
    float4 q = *(const float4*)&g_qa[(size_t)dst * 256 + h * 128 + lane * 4];

    float m = -INFINITY, ssum = 0.f;
    float4 acc = make_float4(0.f, 0.f, 0.f, 0.f);
    for (int p = beg; p < end; p++) {
        int s = g_csr[p];
        const float* kb = &g_kv[(size_t)s * 512 + h * 128 + lane * 4];
        float4 k = *(const float4*)kb;
        float4 v = *(const float4*)(kb + 256);
        float d = q.x * k.x + q.y * k.y + q.z * k.z + q.w * k.w;
#pragma unroll
        for (int o = 16; o > 0; o >>= 1) d += __shfl_xor_sync(0xffffffffu, d, o);
        d *= scale;
        float mn = fmaxf(m, d);
        float corr = __expf(m - mn);      // first iter: exp(-inf) = 0
        float w = __expf(d - mn);
        ssum = ssum * corr + w;
        acc.x = acc.x * corr + w * v.x;
        acc.y = acc.y * corr + w * v.y;
        acc.z = acc.z * corr + w * v.z;
        acc.w = acc.w * corr + w * v.w;
        m = mn;
    }
    float inv = 1.f / (ssum + 1e-16f);
    float o[4] = {acc.x * inv, acc.y * inv, acc.z * inv, acc.w * inv};
#pragma unroll
    for (int j = 0; j < 4; j++)          // exact gelu
        o[j] = 0.5f * o[j] * (1.f + erff(o[j] * 0.7071067811865475f));
    float4 w4 = make_float4(o[0], o[1], o[2], o[3]);
    *(float4*)&g_agg[(size_t)dst * 256 + h * 128 + lane * 4] = w4;
}

// ---------------------------------------------------------------------------
// Decoder rows: z_in[r,:] = za[nodes[r],:] @ W_dec + b_dec
// ---------------------------------------------------------------------------
__global__ void zin_kernel(const int* __restrict__ nodes,
                           const float* __restrict__ Wdec,
                           const float* __restrict__ bdec)
{
    __shared__ float row[256];
    int r = blockIdx.x, t = threadIdx.x;
    row[t] = g_za[(size_t)nodes[r] * 256 + t];
    __syncthreads();
    float s = bdec[t];
#pragma unroll 8
    for (int k = 0; k < 256; k++) s += row[k] * Wdec[k * 256 + t];
    g_zin[r * 256 + t] = s;
}

// ---------------------------------------------------------------------------
// Host launcher
// ---------------------------------------------------------------------------
static inline void launch_gemm(int M, int N, int K,
                               const float* A, int lda,
                               const float* B, int ldb,
                               float* C, int ldc,
                               const float* bias, int act,
                               const float* aux = nullptr,
                               const float* skipp = nullptr)
{
    dim3 grid((N + 127) / 128, (M + 127) / 128);
    mm_nt<<<grid, 256>>>(M, N, K, A, lda, B, ldb, C, ldc, bias, act, aux, skipp);
}

extern "C" void kernel_launch(void* const* d_in, const int* in_sizes, int n_in,
                              void* d_out, int out_size)
{
    const float* x_author    = (const float*)d_in[0];
    const float* x_paper     = (const float*)d_in[1];
    const int*   edge_b_src  = (const int*)d_in[4];
    const int*   edge_b_dst  = (const int*)d_in[5];
    const int*   input_nodes = (const int*)d_in[6];
    const float* W_in_a  = (const float*)d_in[7];
    const float* b_in_a  = (const float*)d_in[8];
    const float* W_in_p  = (const float*)d_in[9];
    const float* b_in_p  = (const float*)d_in[10];
    const float* Wkqv_a  = (const float*)d_in[11];
    const float* bkqv_a  = (const float*)d_in[12];
    const float* Wkqv_p  = (const float*)d_in[13];
    const float* bkqv_p  = (const float*)d_in[14];
    const float* Wk_rel_b = (const float*)d_in[17];
    const float* Wv_rel_b = (const float*)d_in[18];
    const float* p_b     = (const float*)d_in[20];
    const float* Wout_a  = (const float*)d_in[21];
    const float* bout_a  = (const float*)d_in[22];
    const float* skip_a  = (const float*)d_in[25];
    const float* W_dec   = (const float*)d_in[27];
    const float* b_dec   = (const float*)d_in[28];

    const int Na = in_sizes[0] / 128;
    const int Np = in_sizes[1] / 128;
    const int E  = in_sizes[4];
    const int NI = in_sizes[6];

    float *xa, *xp, *qa, *kv, *agg, *za, *zin, *wft, *bf;
    float *wina_t, *winp_t, *wq_t, *wout_t;
    cudaGetSymbolAddress((void**)&xa,  g_xa);
    cudaGetSymbolAddress((void**)&xp,  g_xp);
    cudaGetSymbolAddress((void**)&qa,  g_qa);
    cudaGetSymbolAddress((void**)&kv,  g_kv);
    cudaGetSymbolAddress((void**)&agg, g_agg);
    cudaGetSymbolAddress((void**)&za,  g_za);
    cudaGetSymbolAddress((void**)&zin, g_zin);
    cudaGetSymbolAddress((void**)&wft, g_wft);
    cudaGetSymbolAddress((void**)&bf,  g_bf);
    cudaGetSymbolAddress((void**)&wina_t, g_wina_t);
    cudaGetSymbolAddress((void**)&winp_t, g_winp_t);
    cudaGetSymbolAddress((void**)&wq_t,   g_wq_t);
    cudaGetSymbolAddress((void**)&wout_t, g_wout_t);

    dim3 trb(32, 8);

    // 1. fused k/v relation weights (transposed)
    fuse_kernel<<<512, 256>>>(Wkqv_p, Wk_rel_b, Wv_rel_b);
    // 2. W_in_p^T
    tr_kernel<<<dim3(8, 4), trb>>>(W_in_p, 256, winp_t, 128, 256);
    // 3. xp = relu(x_paper @ W_in_p + b)
    launch_gemm(Np, 256, 128, x_paper, 128, winp_t, 128, xp, 256, b_in_p, 1);
    // 4. fused bias
    bias_fuse_kernel<<<4, 128>>>(bkqv_p, Wk_rel_b, Wv_rel_b);
    // 5. W_in_a^T
    tr_kernel<<<dim3(8, 4), trb>>>(W_in_a, 256, wina_t, 128, 256);
    // 6. kv = xp @ wf^T + bf   [Np, 512]   <-- ncu -s 5 profiles this launch
    launch_gemm(Np, 512, 256, xp, 256, wft, 256, kv, 512, bf, 0);
    // 7. Wq^T (q-slice of Wkqv_a)
    tr_kernel<<<dim3(8, 8), trb>>>(Wkqv_a + 256, 768, wq_t, 256, 256);
    // 8. xa = relu(x_author @ W_in_a + b)
    launch_gemm(Na, 256, 128, x_author, 128, wina_t, 128, xa, 256, b_in_a, 1);
    // 9. qa = xa @ Wq + b
    launch_gemm(Na, 256, 256, xa, 256, wq_t, 256, qa, 256, bkqv_a + 256, 0);
    // 10. Wout^T
    tr_kernel<<<dim3(8, 8), trb>>>(Wout_a, 256, wout_t, 256, 256);
    // 11-14. CSR over edge_b (paper -> author)
    zero_deg_kernel<<<(Na + 256) / 256, 256>>>(Na);
    hist_kernel<<<(E + 255) / 256, 256>>>(edge_b_dst, E);
    scan_kernel<<<1, 1024>>>(Na);
    scatter_kernel<<<(E + 255) / 256, 256>>>(edge_b_src, edge_b_dst, E);
    // 15. attention (single-pass online softmax, gelu fused)
    {
        long long warps = (long long)Na * 2;
        int blocks = (int)((warps * 32 + 255) / 256);
        attn_kernel<<<blocks, 256>>>(Na, p_b);
    }
    // 16. za = ga*(gelu_agg @ Wout + bout) + (1-ga)*xa   (act=3)
    launch_gemm(Na, 256, 256, agg, 256, wout_t, 256, za, 256, bout_a, 3, xa, skip_a);
    // 17. decoder rows
    zin_kernel<<<NI, 256>>>(input_nodes, W_dec, b_dec);
    // 18. out = sigmoid(zin @ za^T)   [NI, Na]
    launch_gemm(NI, Na, 256, zin, 256, za, 256, (float*)d_out, Na, nullptr, 2);
}

// round 6
// speedup vs baseline: 1.5066x; 1.5066x over previous
#include <cuda_runtime.h>
#include <cuda_bf16.h>
#include <math.h>
#include <stdint.h>

// ---------------------------------------------------------------------------
// Problem constants
// ---------------------------------------------------------------------------
#define MAX_N  50048
#define MAX_E  800000
#define MAX_NI 2048

// ---------------------------------------------------------------------------
// Static device scratch
// ---------------------------------------------------------------------------
__device__ float g_xa  [MAX_N * 256];
__device__ float g_xp  [MAX_N * 256];
__device__ float g_qa  [MAX_N * 256];
__device__ float g_kv  [MAX_N * 512];   // per node: [ke_h0|ke_h1|ve_h0|ve_h1]
__device__ float g_agg [MAX_N * 256];   // gelu(attention out)
__device__ float g_za  [MAX_N * 256];
__device__ float g_zin [MAX_NI * 256];
__device__ float g_wft [512 * 256];     // fused k/v weights, TRANSPOSED [out][in]
__device__ float g_bf  [512];
__device__ float g_wina_t[256 * 128];
__device__ float g_winp_t[256 * 128];
__device__ float g_wq_t  [256 * 256];
__device__ float g_wout_t[256 * 256];
__device__ int   g_deg [MAX_N + 1];
__device__ int   g_off [MAX_N + 1];
__device__ int   g_cur [MAX_N];
__device__ int   g_csr [MAX_E];

// ===========================================================================
// Split-bf16 tensor-core NT GEMM:  C[M,N] = act( A[M,K] * B[N,K]^T + bias )
// smem rows: [hi(16) | lo(16)] bf16 per 16-k chunk, stride 40 (conflict-free
// for ldmatrix). Per k16: Ah*Bh + Ah*Bl + Al*Bh, issued TERM-MAJOR so that
// consecutive MMAs hit independent accumulators (dep gap = 8).
// Block 128x128, 8 warps (4m x 2n), warp tile 32x64.
// act: 0 none, 1 relu, 2 sigmoid, 3 gated residual ga*v+(1-ga)*aux
// ===========================================================================
#define SMSTR 40   // bf16 stride per row (16 hi + 16 lo + 8 pad)

__device__ __forceinline__ uint32_t smem_u32(const void* p) {
    uint32_t a;
    asm("{ .reg .u64 t; cvta.to.shared.u64 t, %1; cvt.u32.u64 %0, t; }"
        : "=r"(a) : "l"(p));
    return a;
}

#define LDSM4(r0, r1, r2, r3, addr) \
    asm volatile("ldmatrix.sync.aligned.m8n8.x4.shared.b16 {%0,%1,%2,%3}, [%4];" \
                 : "=r"(r0), "=r"(r1), "=r"(r2), "=r"(r3) : "r"(addr))

#define MMA16816(acc, a0, a1, a2, a3, b0, b1) \
    asm volatile("mma.sync.aligned.m16n8k16.row.col.f32.bf16.bf16.f32 " \
                 "{%0,%1,%2,%3}, {%4,%5,%6,%7}, {%8,%9}, {%0,%1,%2,%3};\n" \
                 : "+f"((acc)[0]), "+f"((acc)[1]), "+f"((acc)[2]), "+f"((acc)[3]) \
                 : "r"(a0), "r"(a1), "r"(a2), "r"(a3), "r"(b0), "r"(b1))

__global__ void __launch_bounds__(256, 2)
mm_nt(int M, int N, int K,
      const float* __restrict__ A, int lda,
      const float* __restrict__ B, int ldb,
      float* __restrict__ C, int ldc,
      const float* __restrict__ bias, int act,
      const float* __restrict__ aux, const float* __restrict__ skipp)
{
    __shared__ __align__(16) __nv_bfloat16 As[128 * SMSTR];
    __shared__ __align__(16) __nv_bfloat16 Bs[128 * SMSTR];

    const int m0 = blockIdx.y * 128;
    const int n0 = blockIdx.x * 128;
    const int tid  = threadIdx.x;
    const int warp = tid >> 5, lane = tid & 31;
    const int g  = lane >> 2, tg = lane & 3;
    const int wm = warp >> 1, wn = warp & 1;        // 4m x 2n warps
    const int l15 = lane & 15, l16 = lane >> 4;

    const uint32_t asb = smem_u32(As), bsb = smem_u32(Bs);

    float acc[2][8][4];
#pragma unroll
    for (int i = 0; i < 2; i++)
#pragma unroll
        for (int j = 0; j < 8; j++)
#pragma unroll
            for (int e = 0; e < 4; e++) acc[i][j][e] = 0.f;

    // staging map: each thread = one row-half (8 k) of A and of B
    const int srow = tid >> 1, shalf = tid & 1;
    const float4 z4 = make_float4(0.f, 0.f, 0.f, 0.f);
    float4 ra[2], rb[2];

    const int KT = K >> 4;
    const int mrows = (M - m0 > 128) ? 128 : (M - m0);
    const int nrows = (N - n0 > 128) ? 128 : (N - n0);
    const bool aok = srow < mrows, bok = srow < nrows;
    const float* ap = A + (size_t)(m0 + srow) * lda + shalf * 8;
    const float* bp = B + (size_t)(n0 + srow) * ldb + shalf * 8;

    // prefetch tile 0
    ra[0] = aok ? *(const float4*)(ap + 0) : z4;
    ra[1] = aok ? *(const float4*)(ap + 4) : z4;
    rb[0] = bok ? *(const float4*)(bp + 0) : z4;
    rb[1] = bok ? *(const float4*)(bp + 4) : z4;

    for (int kt = 0; kt < KT; kt++) {
        // ---- convert + store (hi at col k, lo at col 16+k) ----
#pragma unroll
        for (int q = 0; q < 2; q++) {
            float va[4] = {ra[q].x, ra[q].y, ra[q].z, ra[q].w};
            float vb[4] = {rb[q].x, rb[q].y, rb[q].z, rb[q].w};
            uint64_t ah = 0, al = 0, bh = 0, bl = 0;
#pragma unroll
            for (int j = 0; j < 4; j++) {
                __nv_bfloat16 h = __float2bfloat16_rn(va[j]);
                __nv_bfloat16 l = __float2bfloat16_rn(va[j] - __bfloat162float(h));
                ah |= (uint64_t)__bfloat16_as_ushort(h) << (16 * j);
                al |= (uint64_t)__bfloat16_as_ushort(l) << (16 * j);
                h = __float2bfloat16_rn(vb[j]);
                l = __float2bfloat16_rn(vb[j] - __bfloat162float(h));
                bh |= (uint64_t)__bfloat16_as_ushort(h) << (16 * j);
                bl |= (uint64_t)__bfloat16_as_ushort(l) << (16 * j);
            }
            int kc = shalf * 8 + 4 * q;          // 0..15
            *(uint64_t*)&As[srow * SMSTR + kc]      = ah;
            *(uint64_t*)&As[srow * SMSTR + 16 + kc] = al;
            *(uint64_t*)&Bs[srow * SMSTR + kc]      = bh;
            *(uint64_t*)&Bs[srow * SMSTR + 16 + kc] = bl;
        }
        __syncthreads();

        // ---- prefetch next tile ----
        if (kt + 1 < KT) {
            const float* a2 = ap + (kt + 1) * 16;
            const float* b2 = bp + (kt + 1) * 16;
            ra[0] = aok ? *(const float4*)(a2 + 0) : z4;
            ra[1] = aok ? *(const float4*)(a2 + 4) : z4;
            rb[0] = bok ? *(const float4*)(b2 + 0) : z4;
            rb[1] = bok ? *(const float4*)(b2 + 4) : z4;
        }

        // ---- A fragments (hi + lo) via ldmatrix ----
        uint32_t ahf[2][4], alf[2][4];
#pragma unroll
        for (int mt = 0; mt < 2; mt++) {
            int row = wm * 32 + mt * 16 + l15;
            uint32_t a_ad = asb + row * (SMSTR * 2) + l16 * 16;
            LDSM4(ahf[mt][0], ahf[mt][1], ahf[mt][2], ahf[mt][3], a_ad);
            LDSM4(alf[mt][0], alf[mt][1], alf[mt][2], alf[mt][3], a_ad + 32);
        }

        // ---- B in pairs of n16; TERM-MAJOR mma issue (8 indep per term) ----
#pragma unroll
        for (int npp = 0; npp < 2; npp++) {
            uint32_t bhf[2][4], blf[2][4];
#pragma unroll
            for (int q = 0; q < 2; q++) {
                int row = wn * 64 + (npp * 2 + q) * 16 + l15;
                uint32_t b_ad = bsb + row * (SMSTR * 2) + l16 * 16;
                LDSM4(bhf[q][0], bhf[q][1], bhf[q][2], bhf[q][3], b_ad);
                LDSM4(blf[q][0], blf[q][1], blf[q][2], blf[q][3], b_ad + 32);
            }
            // term 1: Ah * Bh
#pragma unroll
            for (int q = 0; q < 2; q++)
#pragma unroll
                for (int mt = 0; mt < 2; mt++)
#pragma unroll
                    for (int j = 0; j < 2; j++)
                        MMA16816(acc[mt][(npp * 2 + q) * 2 + j],
                                 ahf[mt][0], ahf[mt][1], ahf[mt][2], ahf[mt][3],
                                 bhf[q][j], bhf[q][2 + j]);
            // term 2: Ah * Bl
#pragma unroll
            for (int q = 0; q < 2; q++)
#pragma unroll
                for (int mt = 0; mt < 2; mt++)
#pragma unroll
                    for (int j = 0; j < 2; j++)
                        MMA16816(acc[mt][(npp * 2 + q) * 2 + j],
                                 ahf[mt][0], ahf[mt][1], ahf[mt][2], ahf[mt][3],
                                 blf[q][j], blf[q][2 + j]);
            // term 3: Al * Bh
#pragma unroll
            for (int q = 0; q < 2; q++)
#pragma unroll
                for (int mt = 0; mt < 2; mt++)
#pragma unroll
                    for (int j = 0; j < 2; j++)
                        MMA16816(acc[mt][(npp * 2 + q) * 2 + j],
                                 alf[mt][0], alf[mt][1], alf[mt][2], alf[mt][3],
                                 bhf[q][j], bhf[q][2 + j]);
        }
        __syncthreads();
    }

    // ---- epilogue ----
    float ga = 0.f;
    if (act == 3) ga = 1.f / (1.f + __expf(-skipp[0]));

#pragma unroll
    for (int mt = 0; mt < 2; mt++) {
#pragma unroll
        for (int nt = 0; nt < 8; nt++) {
            int r0 = m0 + wm * 32 + mt * 16 + g;
            int cc = n0 + wn * 64 + nt * 8 + 2 * tg;
            if (cc < N) {
                float b0 = bias ? bias[cc] : 0.f;
                float b1 = bias ? bias[cc + 1] : 0.f;
                float v0 = acc[mt][nt][0] + b0, v1 = acc[mt][nt][1] + b1;
                float v2 = acc[mt][nt][2] + b0, v3 = acc[mt][nt][3] + b1;
                if (act == 1) {
                    v0 = fmaxf(v0, 0.f); v1 = fmaxf(v1, 0.f);
                    v2 = fmaxf(v2, 0.f); v3 = fmaxf(v3, 0.f);
                } else if (act == 2) {
                    v0 = 1.f / (1.f + __expf(-v0)); v1 = 1.f / (1.f + __expf(-v1));
                    v2 = 1.f / (1.f + __expf(-v2)); v3 = 1.f / (1.f + __expf(-v3));
                } else if (act == 3) {
                    if (r0 < M) {
                        v0 = ga * v0 + (1.f - ga) * aux[(size_t)r0 * 256 + cc];
                        v1 = ga * v1 + (1.f - ga) * aux[(size_t)r0 * 256 + cc + 1];
                    }
                    if (r0 + 8 < M) {
                        v2 = ga * v2 + (1.f - ga) * aux[(size_t)(r0 + 8) * 256 + cc];
                        v3 = ga * v3 + (1.f - ga) * aux[(size_t)(r0 + 8) * 256 + cc + 1];
                    }
                }
                if (r0 < M)     { float2 p = {v0, v1}; *(float2*)&C[(size_t)r0 * ldc + cc] = p; }
                if (r0 + 8 < M) { float2 p = {v2, v3}; *(float2*)&C[(size_t)(r0 + 8) * ldc + cc] = p; }
            }
        }
    }
}

// ---------------------------------------------------------------------------
// All 4 weight transposes in ONE launch. blockIdx.z selects the matrix.
// out[n*K + k] = in[k*ldin + n]
// ---------------------------------------------------------------------------
__global__ void tr_all(const float* __restrict__ Wp, const float* __restrict__ Wa,
                       const float* __restrict__ Wq, const float* __restrict__ Wo)
{
    __shared__ float t[32][33];
    const float* in; float* out; int ldin, K, N;
    switch (blockIdx.z) {
        case 0: in = Wp; out = g_winp_t; ldin = 256; K = 128; N = 256; break;
        case 1: in = Wa; out = g_wina_t; ldin = 256; K = 128; N = 256; break;
        case 2: in = Wq; out = g_wq_t;   ldin = 768; K = 256; N = 256; break;
        default: in = Wo; out = g_wout_t; ldin = 256; K = 256; N = 256; break;
    }
    int bx = blockIdx.x * 32, by = blockIdx.y * 32;
    if (bx >= N || by >= K) return;
    int x = bx + threadIdx.x;
    for (int dy = 0; dy < 32; dy += 8) {
        int y = by + threadIdx.y + dy;
        if (x < N && y < K) t[threadIdx.y + dy][threadIdx.x] = in[(size_t)y * ldin + x];
    }
    __syncthreads();
    int x2 = by + threadIdx.x;
    for (int dy = 0; dy < 32; dy += 8) {
        int y2 = bx + threadIdx.y + dy;
        if (x2 < K && y2 < N) out[(size_t)y2 * K + x2] = t[threadIdx.x][threadIdx.y + dy];
    }
}

// ---------------------------------------------------------------------------
// Fused relation weights (transposed output):
// g_wft[c][r] = sum_d Wkqv_p[r][part + h*128 + d] * R[h][d][e]
// ---------------------------------------------------------------------------
__global__ void fuse_kernel(const float* __restrict__ Wkqv_p,
                            const float* __restrict__ Rk,
                            const float* __restrict__ Rv)
{
    int idx = blockIdx.x * 256 + threadIdx.x;     // 512*256
    int c = idx >> 8, r = idx & 255;
    int isv = c >> 8, h = (c >> 7) & 1, e = c & 127;
    const float* R = (isv ? Rv : Rk) + h * 16384;
    const float* w = Wkqv_p + (size_t)r * 768 + (isv ? 512 : 0) + h * 128;
    float s = 0.f;
#pragma unroll 8
    for (int d = 0; d < 128; d++) s += w[d] * R[d * 128 + e];
    g_wft[c * 256 + r] = s;
}

// warp per output (512 warps total)
__global__ void bias_fuse_kernel(const float* __restrict__ bkqv,
                                 const float* __restrict__ Rk,
                                 const float* __restrict__ Rv)
{
    int gw = (blockIdx.x * 256 + threadIdx.x) >> 5;
    int lane = threadIdx.x & 31;
    if (gw >= 512) return;
    int isv = gw >> 8, h = (gw >> 7) & 1, e = gw & 127;
    const float* R = (isv ? Rv : Rk) + h * 16384;
    const float* b = bkqv + (isv ? 512 : 0) + h * 128;
    float s = 0.f;
#pragma unroll
    for (int i = 0; i < 4; i++) {
        int d = lane + 32 * i;
        s += b[d] * R[d * 128 + e];
    }
#pragma unroll
    for (int o = 16; o > 0; o >>= 1) s += __shfl_xor_sync(0xffffffffu, s, o);
    if (lane == 0) g_bf[gw] = s;
}

// ---------------------------------------------------------------------------
// CSR build
// ---------------------------------------------------------------------------
__global__ void zero_deg_kernel(int n)
{
    int i = blockIdx.x * blockDim.x + threadIdx.x;
    if (i <= n) g_deg[i] = 0;
}
__global__ void hist_kernel(const int* __restrict__ dst, int E)
{
    int e = blockIdx.x * blockDim.x + threadIdx.x;
    if (e < E) atomicAdd(&g_deg[dst[e]], 1);
}
__global__ void __launch_bounds__(1024) scan_kernel(int n)
{
    __shared__ int part[1024];
    int t = threadIdx.x;
    int chunk = (n + 1023) >> 10;
    int b = t * chunk, e = min(b + chunk, n);
    int s = 0;
    for (int i = b; i < e; i++) s += g_deg[i];
    part[t] = s;
    __syncthreads();
    for (int o = 1; o < 1024; o <<= 1) {
        int v = (t >= o) ? part[t - o] : 0;
        __syncthreads();
        part[t] += v;
        __syncthreads();
    }
    int run = (t == 0) ? 0 : part[t - 1];
    for (int i = b; i < e; i++) {
        g_off[i] = run; g_cur[i] = run; run += g_deg[i];
    }
    if (t == 0) g_off[n] = part[1023];
}
__global__ void scatter_kernel(const int* __restrict__ src,
                               const int* __restrict__ dst, int E)
{
    int e = blockIdx.x * blockDim.x + threadIdx.x;
    if (e < E) {
        int p = atomicAdd(&g_cur[dst[e]], 1);
        g_csr[p] = src[e];
    }
}

// ---------------------------------------------------------------------------
// Attention: warp per (dst, head), single-pass online softmax, gelu fused.
// ---------------------------------------------------------------------------
__global__ void attn_kernel(int Na, const float* __restrict__ p_rel)
{
    int gw = (blockIdx.x * 256 + threadIdx.x) >> 5;
    int lane = threadIdx.x & 31;
    if (gw >= Na * 2) return;
    int dst = gw >> 1, h = gw & 1;

    int beg = g_off[dst], end = g_off[dst + 1];
    float scale = p_rel[h] * 0.08838834764831845f;   // p / sqrt(128)
    float4 q = *(const float4*)&g_qa[(size_t)dst * 256 + h * 128 + lane * 4];

    float m = -INFINITY, ssum = 0.f;
    float4 acc = make_float4(0.f, 0.f, 0.f, 0.f);
    for (int p = beg; p < end; p++) {
        int s = g_csr[p];
        const float* kb = &g_kv[(size_t)s * 512 + h * 128 + lane * 4];
        float4 k = *(const float4*)kb;
        float4 v = *(const float4*)(kb + 256);
        float d = q.x * k.x + q.y * k.y + q.z * k.z + q.w * k.w;
#pragma unroll
        for (int o = 16; o > 0; o >>= 1) d += __shfl_xor_sync(0xffffffffu, d, o);
        d *= scale;
        float mn = fmaxf(m, d);
        float corr = __expf(m - mn);      // first iter: exp(-inf) = 0
        float w = __expf(d - mn);
        ssum = ssum * corr + w;
        acc.x = acc.x * corr + w * v.x;
        acc.y = acc.y * corr + w * v.y;
        acc.z = acc.z * corr + w * v.z;
        acc.w = acc.w * corr + w * v.w;
        m = mn;
    }
    float inv = 1.f / (ssum + 1e-16f);
    float o[4] = {acc.x * inv, acc.y * inv, acc.z * inv, acc.w * inv};
#pragma unroll
    for (int j = 0; j < 4; j++)          // exact gelu
        o[j] = 0.5f * o[j] * (1.f + erff(o[j] * 0.7071067811865475f));
    float4 w4 = make_float4(o[0], o[1], o[2], o[3]);
    *(float4*)&g_agg[(size_t)dst * 256 + h * 128 + lane * 4] = w4;
}

// ---------------------------------------------------------------------------
// Decoder rows: z_in[r,:] = za[nodes[r],:] @ W_dec + b_dec
// ---------------------------------------------------------------------------
__global__ void zin_kernel(const int* __restrict__ nodes,
                           const float* __restrict__ Wdec,
                           const float* __restrict__ bdec)
{
    __shared__ float row[256];
    int r = blockIdx.x, t = threadIdx.x;
    row[t] = g_za[(size_t)nodes[r] * 256 + t];
    __syncthreads();
    float s = bdec[t];
#pragma unroll 8
    for (int k = 0; k < 256; k++) s += row[k] * Wdec[k * 256 + t];
    g_zin[r * 256 + t] = s;
}

// ---------------------------------------------------------------------------
// Host launcher
// ---------------------------------------------------------------------------
static inline void launch_gemm(int M, int N, int K,
                               const float* A, int lda,
                               const float* B, int ldb,
                               float* C, int ldc,
                               const float* bias, int act,
                               const float* aux = nullptr,
                               const float* skipp = nullptr)
{
    dim3 grid((N + 127) / 128, (M + 127) / 128);
    mm_nt<<<grid, 256>>>(M, N, K, A, lda, B, ldb, C, ldc, bias, act, aux, skipp);
}

extern "C" void kernel_launch(void* const* d_in, const int* in_sizes, int n_in,
                              void* d_out, int out_size)
{
    const float* x_author    = (const float*)d_in[0];
    const float* x_paper     = (const float*)d_in[1];
    const int*   edge_b_src  = (const int*)d_in[4];
    const int*   edge_b_dst  = (const int*)d_in[5];
    const int*   input_nodes = (const int*)d_in[6];
    const float* W_in_a  = (const float*)d_in[7];
    const float* b_in_a  = (const float*)d_in[8];
    const float* W_in_p  = (const float*)d_in[9];
    const float* b_in_p  = (const float*)d_in[10];
    const float* Wkqv_a  = (const float*)d_in[11];
    const float* bkqv_a  = (const float*)d_in[12];
    const float* Wkqv_p  = (const float*)d_in[13];
    const float* bkqv_p  = (const float*)d_in[14];
    const float* Wk_rel_b = (const float*)d_in[17];
    const float* Wv_rel_b = (const float*)d_in[18];
    const float* p_b     = (const float*)d_in[20];
    const float* Wout_a  = (const float*)d_in[21];
    const float* bout_a  = (const float*)d_in[22];
    const float* skip_a  = (const float*)d_in[25];
    const float* W_dec   = (const float*)d_in[27];
    const float* b_dec   = (const float*)d_in[28];

    const int Na = in_sizes[0] / 128;
    const int Np = in_sizes[1] / 128;
    const int E  = in_sizes[4];
    const int NI = in_sizes[6];

    float *xa, *xp, *qa, *kv, *agg, *za, *zin, *wft;
    float *wina_t, *winp_t, *wq_t, *wout_t, *bf;
    cudaGetSymbolAddress((void**)&xa,  g_xa);
    cudaGetSymbolAddress((void**)&xp,  g_xp);
    cudaGetSymbolAddress((void**)&qa,  g_qa);
    cudaGetSymbolAddress((void**)&kv,  g_kv);
    cudaGetSymbolAddress((void**)&agg, g_agg);
    cudaGetSymbolAddress((void**)&za,  g_za);
    cudaGetSymbolAddress((void**)&zin, g_zin);
    cudaGetSymbolAddress((void**)&wft, g_wft);
    cudaGetSymbolAddress((void**)&bf,  g_bf);
    cudaGetSymbolAddress((void**)&wina_t, g_wina_t);
    cudaGetSymbolAddress((void**)&winp_t, g_winp_t);
    cudaGetSymbolAddress((void**)&wq_t,   g_wq_t);
    cudaGetSymbolAddress((void**)&wout_t, g_wout_t);

    // 0. fused k/v relation weights (transposed)
    fuse_kernel<<<512, 256>>>(Wkqv_p, Wk_rel_b, Wv_rel_b);
    // 1. all weight transposes (one launch)
    tr_all<<<dim3(8, 8, 4), dim3(32, 8)>>>(W_in_p, W_in_a, Wkqv_a + 256, Wout_a);
    // 2. fused bias
    bias_fuse_kernel<<<64, 256>>>(bkqv_p, Wk_rel_b, Wv_rel_b);
    // 3. xp = relu(x_paper @ W_in_p + b)
    launch_gemm(Np, 256, 128, x_paper, 128, winp_t, 128, xp, 256, b_in_p, 1);
    // 4. xa = relu(x_author @ W_in_a + b)
    launch_gemm(Na, 256, 128, x_author, 128, wina_t, 128, xa, 256, b_in_a, 1);
    // 5. kv = xp @ wf^T + bf   [Np, 512]   <-- ncu -s 5 profiles this launch
    launch_gemm(Np, 512, 256, xp, 256, wft, 256, kv, 512, bf, 0);
    // 6. qa = xa @ Wq + b
    launch_gemm(Na, 256, 256, xa, 256, wq_t, 256, qa, 256, bkqv_a + 256, 0);
    // 7-10. CSR over edge_b (paper -> author)
    zero_deg_kernel<<<(Na + 256) / 256, 256>>>(Na);
    hist_kernel<<<(E + 255) / 256, 256>>>(edge_b_dst, E);
    scan_kernel<<<1, 1024>>>(Na);
    scatter_kernel<<<(E + 255) / 256, 256>>>(edge_b_src, edge_b_dst, E);
    // 11. attention (single-pass online softmax, gelu fused)
    {
        long long warps = (long long)Na * 2;
        int blocks = (int)((warps * 32 + 255) / 256);
        attn_kernel<<<blocks, 256>>>(Na, p_b);
    }
    // 12. za = ga*(gelu_agg @ Wout + bout) + (1-ga)*xa   (act=3)
    launch_gemm(Na, 256, 256, agg, 256, wout_t, 256, za, 256, bout_a, 3, xa, skip_a);
    // 13. decoder rows
    zin_kernel<<<NI, 256>>>(input_nodes, W_dec, b_dec);
    // 14. out = sigmoid(zin @ za^T)   [NI, Na]
    launch_gemm(NI, Na, 256, zin, 256, za, 256, (float*)d_out, Na, nullptr, 2);
}

// round 8
// speedup vs baseline: 1.5745x; 1.0450x over previous
#include <cuda_runtime.h>
#include <cuda_bf16.h>
#include <math.h>
#include <stdint.h>

// ---------------------------------------------------------------------------
// Problem constants
// ---------------------------------------------------------------------------
#define MAX_N  50048
#define MAX_E  800000
#define MAX_NI 2048

// ---------------------------------------------------------------------------
// Static device scratch
// ---------------------------------------------------------------------------
__device__ float g_xa  [MAX_N * 256];
__device__ float g_xp  [MAX_N * 256];
__device__ float g_qa  [MAX_N * 256];
__device__ float g_kv  [MAX_N * 512];   // per node: [ke_h0|ke_h1|ve_h0|ve_h1]
__device__ float g_agg [MAX_N * 256];   // gelu(attention out)
__device__ float g_za  [MAX_N * 256];
__device__ float g_zin [MAX_NI * 256];
__device__ float g_bf  [512];
// hi/lo-bf16 "chunk" format: row stride 2K bf16; per k16 chunk: [hi x16 | lo x16]
__device__ __nv_bfloat16 g_wft_hl [512 * 512];    // fused k/v weights [512][K=256]
__device__ __nv_bfloat16 g_winp_hl[256 * 256];    // [256][K=128]
__device__ __nv_bfloat16 g_wina_hl[256 * 256];
__device__ __nv_bfloat16 g_wq_hl  [256 * 512];    // [256][K=256]
__device__ __nv_bfloat16 g_wout_hl[256 * 512];
__device__ __nv_bfloat16 g_za_hl  [MAX_N * 512];  // [MAX_N][K=256]
__device__ int   g_deg [MAX_N + 1];
__device__ int   g_off [MAX_N + 1];
__device__ int   g_cur [MAX_N];
__device__ int   g_csr [MAX_E];

// ---------------------------------------------------------------------------
// trunc-split: hi = trunc-to-bf16 (exact bit slice), lo = rn(f - hi)
// packs two elements: hi via one PRMT, lo via one cvt.rn.bf16x2
// ---------------------------------------------------------------------------
__device__ __forceinline__ void split2(float f0, float f1,
                                       uint32_t& hi, uint32_t& lo)
{
    uint32_t b0 = __float_as_uint(f0), b1 = __float_as_uint(f1);
    hi = __byte_perm(b0, b1, 0x7632);
    float r0 = f0 - __uint_as_float(b0 & 0xFFFF0000u);
    float r1 = f1 - __uint_as_float(b1 & 0xFFFF0000u);
    __nv_bfloat162 t = __floats2bfloat162_rn(r0, r1);
    lo = *(uint32_t*)&t;
}

__device__ __forceinline__ uint32_t smem_u32(const void* p) {
    uint32_t a;
    asm("{ .reg .u64 t; cvta.to.shared.u64 t, %1; cvt.u32.u64 %0, t; }"
        : "=r"(a) : "l"(p));
    return a;
}

#define LDSM4(r0, r1, r2, r3, addr) \
    asm volatile("ldmatrix.sync.aligned.m8n8.x4.shared.b16 {%0,%1,%2,%3}, [%4];" \
                 : "=r"(r0), "=r"(r1), "=r"(r2), "=r"(r3) : "r"(addr))

#define MMA16816(acc, a0, a1, a2, a3, b0, b1) \
    asm volatile("mma.sync.aligned.m16n8k16.row.col.f32.bf16.bf16.f32 " \
                 "{%0,%1,%2,%3}, {%4,%5,%6,%7}, {%8,%9}, {%0,%1,%2,%3};\n" \
                 : "+f"((acc)[0]), "+f"((acc)[1]), "+f"((acc)[2]), "+f"((acc)[3]) \
                 : "r"(a0), "r"(a1), "r"(a2), "r"(a3), "r"(b0), "r"(b1))

// ===========================================================================
// Split-bf16 NT GEMM: C[M,N] = act( A[M,K](fp32) * Bhl[N][K]^T + bias )
// Bhl is pre-converted hi/lo chunk format (copy-only staging).
// A converted in-kernel via trunc-split. Double-buffered smem, 1 sync/tile.
// Per k16: Ah*Bh + Ah*Bl + Al*Bh, term-major issue.
// act: 0 none, 1 relu, 2 sigmoid, 3 gated residual ga*v+(1-ga)*aux
// ===========================================================================
#define SMSTR 40   // bf16 per smem row: 16 hi + 16 lo + 8 pad

__global__ void __launch_bounds__(256, 2)
mm_nt(int M, int N, int K,
      const float* __restrict__ A, int lda,
      const __nv_bfloat16* __restrict__ Bhl,
      float* __restrict__ C, int ldc,
      const float* __restrict__ bias, int act,
      const float* __restrict__ aux, const float* __restrict__ skipp)
{
    __shared__ __align__(16) __nv_bfloat16 As[2][128 * SMSTR];
    __shared__ __align__(16) __nv_bfloat16 Bs[2][128 * SMSTR];

    const int m0 = blockIdx.y * 128;
    const int n0 = blockIdx.x * 128;
    const int tid  = threadIdx.x;
    const int warp = tid >> 5, lane = tid & 31;
    const int g  = lane >> 4 ? 0 : 0; (void)g;
    const int gq = lane >> 2, tg = lane & 3;
    const int wm = warp >> 1, wn = warp & 1;        // 4m x 2n warps
    const int l15 = lane & 15, l16 = lane >> 4;

    float acc[2][8][4];
#pragma unroll
    for (int i = 0; i < 2; i++)
#pragma unroll
        for (int j = 0; j < 8; j++)
#pragma unroll
            for (int e = 0; e < 4; e++) acc[i][j][e] = 0.f;

    // staging map: thread = (row, k-half of 8)
    const int srow = tid >> 1, shalf = tid & 1;
    const float4 z4 = make_float4(0.f, 0.f, 0.f, 0.f);
    const int KT = K >> 4;
    const int twoK = 2 * K;

    const bool aok = srow < ((M - m0 > 128) ? 128 : (M - m0));
    const float* ap = A + (size_t)(m0 + srow) * lda + shalf * 8;
    const uint4* bp = (const uint4*)(Bhl + (size_t)(n0 + srow) * twoK + shalf * 16);
    // per k16 chunk: B row advances by 32 bf16 = 4 uint4

    float4 ra0, ra1; uint4 rb0, rb1;

    // ---- prefetch tile 0 ----
    ra0 = aok ? *(const float4*)(ap + 0) : z4;
    ra1 = aok ? *(const float4*)(ap + 4) : z4;
    rb0 = bp[0]; rb1 = bp[1];

    // ---- stage tile 0 into buf0 ----
    {
        uint32_t h[4], l[4];
        split2(ra0.x, ra0.y, h[0], l[0]); split2(ra0.z, ra0.w, h[1], l[1]);
        split2(ra1.x, ra1.y, h[2], l[2]); split2(ra1.z, ra1.w, h[3], l[3]);
        uint4* ah = (uint4*)&As[0][srow * SMSTR + shalf * 8];
        ah[0] = make_uint4(h[0], h[1], h[2], h[3]);
        ah[2] = make_uint4(l[0], l[1], l[2], l[3]);   // +16 bf16 = +2 uint4
        uint4* bh = (uint4*)&Bs[0][srow * SMSTR + shalf * 16];
        bh[0] = rb0; bh[1] = rb1;
    }
    __syncthreads();

    for (int kt = 0; kt < KT; kt++) {
        const int cur = kt & 1;
        const bool more = (kt + 1 < KT);
        if (more) {
            const float* a2 = ap + (kt + 1) * 16;
            ra0 = aok ? *(const float4*)(a2 + 0) : z4;
            ra1 = aok ? *(const float4*)(a2 + 4) : z4;
            const uint4* b2 = bp + (kt + 1) * 4;
            rb0 = b2[0]; rb1 = b2[1];
        }

        const uint32_t asb = smem_u32(&As[cur][0]);
        const uint32_t bsb = smem_u32(&Bs[cur][0]);

        // ---- A fragments (hi + lo) ----
        uint32_t ahf[2][4], alf[2][4];
#pragma unroll
        for (int mt = 0; mt < 2; mt++) {
            int row = wm * 32 + mt * 16 + l15;
            uint32_t a_ad = asb + row * (SMSTR * 2) + l16 * 16;
            LDSM4(ahf[mt][0], ahf[mt][1], ahf[mt][2], ahf[mt][3], a_ad);
            LDSM4(alf[mt][0], alf[mt][1], alf[mt][2], alf[mt][3], a_ad + 32);
        }

        // ---- B pairs; term-major issue ----
#pragma unroll
        for (int npp = 0; npp < 2; npp++) {
            uint32_t bhf[2][4], blf[2][4];
#pragma unroll
            for (int q = 0; q < 2; q++) {
                int row = wn * 64 + (npp * 2 + q) * 16 + l15;
                uint32_t b_ad = bsb + row * (SMSTR * 2) + l16 * 16;
                LDSM4(bhf[q][0], bhf[q][1], bhf[q][2], bhf[q][3], b_ad);
                LDSM4(blf[q][0], blf[q][1], blf[q][2], blf[q][3], b_ad + 32);
            }
#pragma unroll
            for (int q = 0; q < 2; q++)
#pragma unroll
                for (int mt = 0; mt < 2; mt++)
#pragma unroll
                    for (int j = 0; j < 2; j++)
                        MMA16816(acc[mt][(npp * 2 + q) * 2 + j],
                                 ahf[mt][0], ahf[mt][1], ahf[mt][2], ahf[mt][3],
                                 bhf[q][j], bhf[q][2 + j]);
#pragma unroll
            for (int q = 0; q < 2; q++)
#pragma unroll
                for (int mt = 0; mt < 2; mt++)
#pragma unroll
                    for (int j = 0; j < 2; j++)
                        MMA16816(acc[mt][(npp * 2 + q) * 2 + j],
                                 ahf[mt][0], ahf[mt][1], ahf[mt][2], ahf[mt][3],
                                 blf[q][j], blf[q][2 + j]);
#pragma unroll
            for (int q = 0; q < 2; q++)
#pragma unroll
                for (int mt = 0; mt < 2; mt++)
#pragma unroll
                    for (int j = 0; j < 2; j++)
                        MMA16816(acc[mt][(npp * 2 + q) * 2 + j],
                                 alf[mt][0], alf[mt][1], alf[mt][2], alf[mt][3],
                                 bhf[q][j], bhf[q][2 + j]);
        }

        if (more) {
            const int nxt = 1 - cur;
            uint32_t h[4], l[4];
            split2(ra0.x, ra0.y, h[0], l[0]); split2(ra0.z, ra0.w, h[1], l[1]);
            split2(ra1.x, ra1.y, h[2], l[2]); split2(ra1.z, ra1.w, h[3], l[3]);
            uint4* ah = (uint4*)&As[nxt][srow * SMSTR + shalf * 8];
            ah[0] = make_uint4(h[0], h[1], h[2], h[3]);
            ah[2] = make_uint4(l[0], l[1], l[2], l[3]);
            uint4* bh = (uint4*)&Bs[nxt][srow * SMSTR + shalf * 16];
            bh[0] = rb0; bh[1] = rb1;
            __syncthreads();
        }
    }

    // ---- epilogue ----
    float ga = 0.f;
    if (act == 3) ga = 1.f / (1.f + __expf(-skipp[0]));

#pragma unroll
    for (int mt = 0; mt < 2; mt++) {
#pragma unroll
        for (int nt = 0; nt < 8; nt++) {
            int r0 = m0 + wm * 32 + mt * 16 + gq;
            int cc = n0 + wn * 64 + nt * 8 + 2 * tg;
            if (cc < N) {
                float b0 = bias ? bias[cc] : 0.f;
                float b1 = bias ? bias[cc + 1] : 0.f;
                float v0 = acc[mt][nt][0] + b0, v1 = acc[mt][nt][1] + b1;
                float v2 = acc[mt][nt][2] + b0, v3 = acc[mt][nt][3] + b1;
                if (act == 1) {
                    v0 = fmaxf(v0, 0.f); v1 = fmaxf(v1, 0.f);
                    v2 = fmaxf(v2, 0.f); v3 = fmaxf(v3, 0.f);
                } else if (act == 2) {
                    v0 = 1.f / (1.f + __expf(-v0)); v1 = 1.f / (1.f + __expf(-v1));
                    v2 = 1.f / (1.f + __expf(-v2)); v3 = 1.f / (1.f + __expf(-v3));
                } else if (act == 3) {
                    if (r0 < M) {
                        v0 = ga * v0 + (1.f - ga) * aux[(size_t)r0 * 256 + cc];
                        v1 = ga * v1 + (1.f - ga) * aux[(size_t)r0 * 256 + cc + 1];
                    }
                    if (r0 + 8 < M) {
                        v2 = ga * v2 + (1.f - ga) * aux[(size_t)(r0 + 8) * 256 + cc];
                        v3 = ga * v3 + (1.f - ga) * aux[(size_t)(r0 + 8) * 256 + cc + 1];
                    }
                }
                if (r0 < M)     { float2 p = {v0, v1}; *(float2*)&C[(size_t)r0 * ldc + cc] = p; }
                if (r0 + 8 < M) { float2 p = {v2, v3}; *(float2*)&C[(size_t)(r0 + 8) * ldc + cc] = p; }
            }
        }
    }
}

// ---------------------------------------------------------------------------
// Weight transposes -> hi/lo chunk format, one launch. z selects matrix.
// logical: out[n][k] = in[k * ldin + n]
// ---------------------------------------------------------------------------
__global__ void tr_all(const float* __restrict__ Wp, const float* __restrict__ Wa,
                       const float* __restrict__ Wq, const float* __restrict__ Wo)
{
    __shared__ float t[32][33];
    const float* in; __nv_bfloat16* out; int ldin, K, N;
    switch (blockIdx.z) {
        case 0: in = Wp; out = g_winp_hl; ldin = 256; K = 128; N = 256; break;
        case 1: in = Wa; out = g_wina_hl; ldin = 256; K = 128; N = 256; break;
        case 2: in = Wq; out = g_wq_hl;   ldin = 768; K = 256; N = 256; break;
        default: in = Wo; out = g_wout_hl; ldin = 256; K = 256; N = 256; break;
    }
    int bx = blockIdx.x * 32, by = blockIdx.y * 32;   // bx: n, by: k
    if (bx >= N || by >= K) return;
    int x = bx + threadIdx.x;
    for (int dy = 0; dy < 32; dy += 8) {
        int y = by + threadIdx.y + dy;
        if (x < N && y < K) t[threadIdx.y + dy][threadIdx.x] = in[(size_t)y * ldin + x];
    }
    __syncthreads();
    if (threadIdx.x < 16) {
        for (int dy = 0; dy < 32; dy += 8) {
            int n_ = bx + threadIdx.y + dy;
            int k0 = by + 2 * threadIdx.x;
            if (n_ < N && k0 < K) {
                float f0 = t[2 * threadIdx.x][threadIdx.y + dy];
                float f1 = t[2 * threadIdx.x + 1][threadIdx.y + dy];
                uint32_t hi, lo;
                split2(f0, f1, hi, lo);
                uint32_t* d = (uint32_t*)(out + (size_t)n_ * 2 * K
                                          + (k0 >> 4) * 32 + (k0 & 15));
                d[0] = hi; d[8] = lo;
            }
        }
    }
}

// ---------------------------------------------------------------------------
// Fused relation weights -> hi/lo chunk format directly.
// wft[c][k] = sum_d Wkqv_p[k][part + h*128 + d] * R[h][d][e], c in [0,512)
// ---------------------------------------------------------------------------
__global__ void fuse_kernel(const float* __restrict__ Wkqv_p,
                            const float* __restrict__ Rk,
                            const float* __restrict__ Rv)
{
    int idx = blockIdx.x * 256 + threadIdx.x;     // 512 * 128
    int c = idx >> 7;          // output row
    int j = idx & 127;         // k pair
    int isv = c >> 8, h = (c >> 7) & 1, e = c & 127;
    const float* R = (isv ? Rv : Rk) + h * 16384;
    const float* w0 = Wkqv_p + (size_t)(2 * j) * 768 + (isv ? 512 : 0) + h * 128;
    const float* w1 = w0 + 768;
    float s0 = 0.f, s1 = 0.f;
#pragma unroll 8
    for (int d = 0; d < 128; d++) {
        float rv = R[d * 128 + e];
        s0 += w0[d] * rv;
        s1 += w1[d] * rv;
    }
    uint32_t hi, lo;
    split2(s0, s1, hi, lo);
    int k = 2 * j;
    uint32_t* dst = (uint32_t*)(g_wft_hl + (size_t)c * 512 + (k >> 4) * 32 + (k & 15));
    dst[0] = hi; dst[8] = lo;
}

// warp per output
__global__ void bias_fuse_kernel(const float* __restrict__ bkqv,
                                 const float* __restrict__ Rk,
                                 const float* __restrict__ Rv)
{
    int gw = (blockIdx.x * 256 + threadIdx.x) >> 5;
    int lane = threadIdx.x & 31;
    if (gw >= 512) return;
    int isv = gw >> 8, h = (gw >> 7) & 1, e = gw & 127;
    const float* R = (isv ? Rv : Rk) + h * 16384;
    const float* b = bkqv + (isv ? 512 : 0) + h * 128;
    float s = 0.f;
#pragma unroll
    for (int i = 0; i < 4; i++) {
        int d = lane + 32 * i;
        s += b[d] * R[d * 128 + e];
    }
#pragma unroll
    for (int o = 16; o > 0; o >>= 1) s += __shfl_xor_sync(0xffffffffu, s, o);
    if (lane == 0) g_bf[gw] = s;
}

// ---------------------------------------------------------------------------
// fp32 -> hi/lo chunk cvt (used for za). Rows >= Rvalid zero-filled.
// ---------------------------------------------------------------------------
__global__ void cvt_hl_kernel(const float* __restrict__ src,
                              __nv_bfloat16* __restrict__ dst,
                              int R, int K, int Rvalid)
{
    int idx = blockIdx.x * 256 + threadIdx.x;
    int halfK = K >> 1;
    if (idx >= R * halfK) return;
    int r = idx / halfK, j = idx - r * halfK;
    int k = 2 * j;
    float f0 = 0.f, f1 = 0.f;
    if (r < Rvalid) {
        float2 p = *(const float2*)&src[(size_t)r * K + k];
        f0 = p.x; f1 = p.y;
    }
    uint32_t hi, lo;
    split2(f0, f1, hi, lo);
    uint32_t* d = (uint32_t*)(dst + (size_t)r * 2 * K + (k >> 4) * 32 + (k & 15));
    d[0] = hi; d[8] = lo;
}

// ---------------------------------------------------------------------------
// CSR build
// ---------------------------------------------------------------------------
__global__ void zero_deg_kernel(int n)
{
    int i = blockIdx.x * blockDim.x + threadIdx.x;
    if (i <= n) g_deg[i] = 0;
}
__global__ void hist_kernel(const int* __restrict__ dst, int E)
{
    int e = blockIdx.x * blockDim.x + threadIdx.x;
    if (e < E) atomicAdd(&g_deg[dst[e]], 1);
}
__global__ void __launch_bounds__(1024) scan_kernel(int n)
{
    __shared__ int part[1024];
    int t = threadIdx.x;
    int chunk = (n + 1023) >> 10;
    int b = t * chunk, e = min(b + chunk, n);
    int s = 0;
    for (int i = b; i < e; i++) s += g_deg[i];
    part[t] = s;
    __syncthreads();
    for (int o = 1; o < 1024; o <<= 1) {
        int v = (t >= o) ? part[t - o] : 0;
        __syncthreads();
        part[t] += v;
        __syncthreads();
    }
    int run = (t == 0) ? 0 : part[t - 1];
    for (int i = b; i < e; i++) {
        g_off[i] = run; g_cur[i] = run; run += g_deg[i];
    }
    if (t == 0) g_off[n] = part[1023];
}
__global__ void scatter_kernel(const int* __restrict__ src,
                               const int* __restrict__ dst, int E)
{
    int e = blockIdx.x * blockDim.x + threadIdx.x;
    if (e < E) {
        int p = atomicAdd(&g_cur[dst[e]], 1);
        g_csr[p] = src[e];
    }
}

// ---------------------------------------------------------------------------
// Attention v2: ONE warp per dst, half-warp per head (lanes 0-15: h0,
// 16-31: h1). 8 floats per lane. 4-shfl reduction within half-warp.
// Single-pass online softmax, 1-edge prefetch pipeline, gelu fused.
// ---------------------------------------------------------------------------
__global__ void attn_kernel(int Na, const float* __restrict__ p_rel)
{
    int gw = (blockIdx.x * 256 + threadIdx.x) >> 5;
    int lane = threadIdx.x & 31;
    if (gw >= Na) return;
    const int dst = gw;
    const int hl = lane >> 4;        // head
    const int l  = lane & 15;

    const int beg = g_off[dst], end = g_off[dst + 1];
    const float scale = p_rel[hl] * 0.08838834764831845f;  // p / sqrt(128)

    const float* qb = &g_qa[(size_t)dst * 256 + hl * 128 + l * 8];
    const float4 q0 = *(const float4*)qb;
    const float4 q1 = *(const float4*)(qb + 4);

    float m = -INFINITY, ssum = 0.f;
    float4 a0 = make_float4(0.f, 0.f, 0.f, 0.f);
    float4 a1 = make_float4(0.f, 0.f, 0.f, 0.f);

    float4 k0, k1, v0, v1;
    if (beg < end) {
        const float* kb = &g_kv[(size_t)g_csr[beg] * 512 + hl * 128 + l * 8];
        k0 = *(const float4*)kb;        k1 = *(const float4*)(kb + 4);
        v0 = *(const float4*)(kb + 256); v1 = *(const float4*)(kb + 260);
    }
    for (int p = beg; p < end; p++) {
        float4 ck0 = k0, ck1 = k1, cv0 = v0, cv1 = v1;
        if (p + 1 < end) {
            const float* kb = &g_kv[(size_t)g_csr[p + 1] * 512 + hl * 128 + l * 8];
            k0 = *(const float4*)kb;        k1 = *(const float4*)(kb + 4);
            v0 = *(const float4*)(kb + 256); v1 = *(const float4*)(kb + 260);
        }
        float d = q0.x * ck0.x + q0.y * ck0.y + q0.z * ck0.z + q0.w * ck0.w
                + q1.x * ck1.x + q1.y * ck1.y + q1.z * ck1.z + q1.w * ck1.w;
#pragma unroll
        for (int o = 8; o > 0; o >>= 1) d += __shfl_xor_sync(0xffffffffu, d, o);
        d *= scale;
        float mn = fmaxf(m, d);
        float corr = __expf(m - mn);      // first iter: exp(-inf) = 0
        float w = __expf(d - mn);
        ssum = ssum * corr + w;
        a0.x = a0.x * corr + w * cv0.x; a0.y = a0.y * corr + w * cv0.y;
        a0.z = a0.z * corr + w * cv0.z; a0.w = a0.w * corr + w * cv0.w;
        a1.x = a1.x * corr + w * cv1.x; a1.y = a1.y * corr + w * cv1.y;
        a1.z = a1.z * corr + w * cv1.z; a1.w = a1.w * corr + w * cv1.w;
        m = mn;
    }
    float inv = 1.f / (ssum + 1e-16f);
    float o[8] = {a0.x * inv, a0.y * inv, a0.z * inv, a0.w * inv,
                  a1.x * inv, a1.y * inv, a1.z * inv, a1.w * inv};
#pragma unroll
    for (int j = 0; j < 8; j++)          // exact gelu
        o[j] = 0.5f * o[j] * (1.f + erff(o[j] * 0.7071067811865475f));
    float* ob = &g_agg[(size_t)dst * 256 + hl * 128 + l * 8];
    *(float4*)ob       = make_float4(o[0], o[1], o[2], o[3]);
    *(float4*)(ob + 4) = make_float4(o[4], o[5], o[6], o[7]);
}

// ---------------------------------------------------------------------------
// Decoder rows: z_in[r,:] = za[nodes[r],:] @ W_dec + b_dec
// ---------------------------------------------------------------------------
__global__ void zin_kernel(const int* __restrict__ nodes,
                           const float* __restrict__ Wdec,
                           const float* __restrict__ bdec)
{
    __shared__ float row[256];
    int r = blockIdx.x, t = threadIdx.x;
    row[t] = g_za[(size_t)nodes[r] * 256 + t];
    __syncthreads();
    float s = bdec[t];
#pragma unroll 8
    for (int k = 0; k < 256; k++) s += row[k] * Wdec[k * 256 + t];
    g_zin[r * 256 + t] = s;
}

// ---------------------------------------------------------------------------
// Host launcher
// ---------------------------------------------------------------------------
static inline void launch_gemm(int M, int N, int K,
                               const float* A, int lda,
                               const __nv_bfloat16* Bhl,
                               float* C, int ldc,
                               const float* bias, int act,
                               const float* aux = nullptr,
                               const float* skipp = nullptr)
{
    dim3 grid((N + 127) / 128, (M + 127) / 128);
    mm_nt<<<grid, 256>>>(M, N, K, A, lda, Bhl, C, ldc, bias, act, aux, skipp);
}

extern "C" void kernel_launch(void* const* d_in, const int* in_sizes, int n_in,
                              void* d_out, int out_size)
{
    const float* x_author    = (const float*)d_in[0];
    const float* x_paper     = (const float*)d_in[1];
    const int*   edge_b_src  = (const int*)d_in[4];
    const int*   edge_b_dst  = (const int*)d_in[5];
    const int*   input_nodes = (const int*)d_in[6];
    const float* W_in_a  = (const float*)d_in[7];
    const float* b_in_a  = (const float*)d_in[8];
    const float* W_in_p  = (const float*)d_in[9];
    const float* b_in_p  = (const float*)d_in[10];
    const float* Wkqv_a  = (const float*)d_in[11];
    const float* bkqv_a  = (const float*)d_in[12];
    const float* Wkqv_p  = (const float*)d_in[13];
    const float* bkqv_p  = (const float*)d_in[14];
    const float* Wk_rel_b = (const float*)d_in[17];
    const float* Wv_rel_b = (const float*)d_in[18];
    const float* p_b     = (const float*)d_in[20];
    const float* Wout_a  = (const float*)d_in[21];
    const float* bout_a  = (const float*)d_in[22];
    const float* skip_a  = (const float*)d_in[25];
    const float* W_dec   = (const float*)d_in[27];
    const float* b_dec   = (const float*)d_in[28];

    const int Na = in_sizes[0] / 128;
    const int Np = in_sizes[1] / 128;
    const int E  = in_sizes[4];
    const int NI = in_sizes[6];

    float *xa, *xp, *qa, *kv, *agg, *za, *zin, *bf;
    __nv_bfloat16 *wft_hl, *winp_hl, *wina_hl, *wq_hl, *wout_hl, *za_hl;
    cudaGetSymbolAddress((void**)&xa,  g_xa);
    cudaGetSymbolAddress((void**)&xp,  g_xp);
    cudaGetSymbolAddress((void**)&qa,  g_qa);
    cudaGetSymbolAddress((void**)&kv,  g_kv);
    cudaGetSymbolAddress((void**)&agg, g_agg);
    cudaGetSymbolAddress((void**)&za,  g_za);
    cudaGetSymbolAddress((void**)&zin, g_zin);
    cudaGetSymbolAddress((void**)&bf,  g_bf);
    cudaGetSymbolAddress((void**)&wft_hl,  g_wft_hl);
    cudaGetSymbolAddress((void**)&winp_hl, g_winp_hl);
    cudaGetSymbolAddress((void**)&wina_hl, g_wina_hl);
    cudaGetSymbolAddress((void**)&wq_hl,   g_wq_hl);
    cudaGetSymbolAddress((void**)&wout_hl, g_wout_hl);
    cudaGetSymbolAddress((void**)&za_hl,   g_za_hl);

    // 0. fused k/v relation weights (hi/lo format)
    fuse_kernel<<<256, 256>>>(Wkqv_p, Wk_rel_b, Wv_rel_b);
    // 1. weight transposes -> hi/lo format (one launch)
    tr_all<<<dim3(8, 8, 4), dim3(32, 8)>>>(W_in_p, W_in_a, Wkqv_a + 256, Wout_a);
    // 2. fused bias
    bias_fuse_kernel<<<64, 256>>>(bkqv_p, Wk_rel_b, Wv_rel_b);
    // 3. xp = relu(x_paper @ W_in_p + b)
    launch_gemm(Np, 256, 128, x_paper, 128, winp_hl, xp, 256, b_in_p, 1);
    // 4. xa = relu(x_author @ W_in_a + b)
    launch_gemm(Na, 256, 128, x_author, 128, wina_hl, xa, 256, b_in_a, 1);
    // 5. kv = xp @ wft^T + bf   [Np, 512]   <-- ncu -s 5 profiles this launch
    launch_gemm(Np, 512, 256, xp, 256, wft_hl, kv, 512, bf, 0);
    // 6. qa = xa @ Wq + b
    launch_gemm(Na, 256, 256, xa, 256, wq_hl, qa, 256, bkqv_a + 256, 0);
    // 7-10. CSR over edge_b (paper -> author)
    zero_deg_kernel<<<(Na + 256) / 256, 256>>>(Na);
    hist_kernel<<<(E + 255) / 256, 256>>>(edge_b_dst, E);
    scan_kernel<<<1, 1024>>>(Na);
    scatter_kernel<<<(E + 255) / 256, 256>>>(edge_b_src, edge_b_dst, E);
    // 11. attention (warp per dst, half-warp per head)
    {
        int blocks = (Na * 32 + 255) / 256;
        attn_kernel<<<blocks, 256>>>(Na, p_b);
    }
    // 12. za = ga*(gelu_agg @ Wout + bout) + (1-ga)*xa   (act=3)
    launch_gemm(Na, 256, 256, agg, 256, wout_hl, za, 256, bout_a, 3, xa, skip_a);
    // 13. za -> hi/lo format (rows >= Na zero-filled)
    cvt_hl_kernel<<<(MAX_N * 128 + 255) / 256, 256>>>(za, za_hl, MAX_N, 256, Na);
    // 14. decoder rows
    zin_kernel<<<NI, 256>>>(input_nodes, W_dec, b_dec);
    // 15. out = sigmoid(zin @ za_hl^T)   [NI, Na]
    launch_gemm(NI, Na, 256, zin, 256, za_hl, (float*)d_out, Na, nullptr, 2);
}